// round 7
// baseline (speedup 1.0000x reference)
#include <cuda_runtime.h>
#include <cstdint>

#define B 64
#define T 512
#define D 1024
#define H 1024
#define G 4096     // 4*H
#define PBLOCKS 64 // persistent grid size

// ---------------- device scratch (no allocations allowed) ----------------
__device__ float g_Zpre[(size_t)T * B * G];   // [t][b][4H] pre-activations
__device__ float g_y0[(size_t)T * B * H];     // layer0 outputs [t][b][H]
__device__ float g_h[2][B * H];               // ping-pong hidden state
__device__ float g_c[B * H];                  // cell state
__device__ volatile int g_bar_count = 0;
__device__ volatile int g_bar_gen = 0;

// ---------------- helpers ----------------
__device__ __forceinline__ unsigned f2tf(float f) {
    unsigned u;
    asm("cvt.rna.tf32.f32 %0, %1;" : "=r"(u) : "f"(f));
    return u;
}

// 3xTF32 split: v = hi + lo (hi captures top 11 bits, lo the next 11)
__device__ __forceinline__ void split_tf(float v, unsigned& hi, unsigned& lo) {
    hi = f2tf(v);
    lo = f2tf(v - __uint_as_float(hi));
}

__device__ __forceinline__ void mma_tf32(float c[4], const unsigned a[4], const unsigned b[2]) {
    asm volatile(
        "mma.sync.aligned.m16n8k8.row.col.f32.tf32.tf32.f32 "
        "{%0,%1,%2,%3}, {%4,%5,%6,%7}, {%8,%9}, {%0,%1,%2,%3};"
        : "+f"(c[0]), "+f"(c[1]), "+f"(c[2]), "+f"(c[3])
        : "r"(a[0]), "r"(a[1]), "r"(a[2]), "r"(a[3]), "r"(b[0]), "r"(b[1]));
}

__device__ __forceinline__ float sigf(float x) {
    return 1.0f / (1.0f + __expf(-x));
}

__device__ __forceinline__ float4 ldcg4(const float* p) {
    return __ldcg((const float4*)p);
}

// Dtype-robust length read (harness passes int64; int32 also handled):
// little-endian int64 => high word of lens[0] is 0; real int32 len >= 1.
__device__ __forceinline__ int read_len(const int* p, int b) {
    int is64 = (p[1] == 0);
    return is64 ? p[2 * b] : p[b];
}

__device__ __forceinline__ void grid_sync() {
    __threadfence();
    __syncthreads();
    if (threadIdx.x == 0) {
        int gen = g_bar_gen;
        if (atomicAdd((int*)&g_bar_count, 1) == PBLOCKS - 1) {
            g_bar_count = 0;
            __threadfence();
            g_bar_gen = gen + 1;
        } else {
            while (g_bar_gen == gen) { __nanosleep(32); }
        }
        __threadfence();
    }
    __syncthreads();
}

// ---------------- init: zero h[0], c ----------------
__global__ void init_state() {
    int i = blockIdx.x * 256 + threadIdx.x;
    if (i < B * H) { g_h[0][i] = 0.0f; g_c[i] = 0.0f; }
}

// ---------------- input GEMM, 3xTF32 ----------------
// M=32768, N=4096, K=1024. Tile 128x128, K-chunk 16 (static smem budget).
// 256 threads = 8 warps (4M x 2N), warp tile 32x64.
__global__ __launch_bounds__(256) void gemm_in(const float* __restrict__ Ax,
                                               const float* __restrict__ W,
                                               const float* __restrict__ bias,
                                               int mode) {
    __shared__ unsigned As[2][128][20];   // [hi/lo][row][k] cols 0..15
    __shared__ unsigned Bs[2][16][132];   // [hi/lo][k][col]

    const int bm = blockIdx.y, bn = blockIdx.x;
    const int tid = threadIdx.x;
    const int wid = tid >> 5, lane = tid & 31;
    const int wm = wid & 3, wn = wid >> 2;
    const int gq = lane >> 2, tg = lane & 3;

    // A loader: 128 rows x 16 cols = 512 float4; rows tid/4 (+64), col (tid%4)*4
    const int arow_l = tid >> 2;          // 0..63
    const int acol = (tid & 3) << 2;
    const float* arp[2];
#pragma unroll
    for (int p = 0; p < 2; p++) {
        int r = bm * 128 + arow_l + p * 64;
        arp[p] = (mode == 0) ? (Ax + ((size_t)(r & (B - 1)) * T + (r >> 6)) * D)
                             : (g_y0 + (size_t)r * H);
    }
    // B loader: 16 k x 128 cols = 512 float4; k tid/32 (+8), col lane*4
    const int brow_l = tid >> 5;
    const int bcol = lane << 2;

    float acc[2][8][4];
#pragma unroll
    for (int mt = 0; mt < 2; mt++)
#pragma unroll
        for (int nt = 0; nt < 8; nt++)
#pragma unroll
            for (int q = 0; q < 4; q++) acc[mt][nt][q] = 0.0f;

    for (int k0 = 0; k0 < 1024; k0 += 16) {
#pragma unroll
        for (int p = 0; p < 2; p++) {
            float4 v = *(const float4*)(arp[p] + k0 + acol);
            int rr = arow_l + p * 64;
            split_tf(v.x, As[0][rr][acol + 0], As[1][rr][acol + 0]);
            split_tf(v.y, As[0][rr][acol + 1], As[1][rr][acol + 1]);
            split_tf(v.z, As[0][rr][acol + 2], As[1][rr][acol + 2]);
            split_tf(v.w, As[0][rr][acol + 3], As[1][rr][acol + 3]);
        }
#pragma unroll
        for (int p = 0; p < 2; p++) {
            int kk = brow_l + p * 8;
            float4 v = *(const float4*)(W + (size_t)(k0 + kk) * G + bn * 128 + bcol);
            split_tf(v.x, Bs[0][kk][bcol + 0], Bs[1][kk][bcol + 0]);
            split_tf(v.y, Bs[0][kk][bcol + 1], Bs[1][kk][bcol + 1]);
            split_tf(v.z, Bs[0][kk][bcol + 2], Bs[1][kk][bcol + 2]);
            split_tf(v.w, Bs[0][kk][bcol + 3], Bs[1][kk][bcol + 3]);
        }
        __syncthreads();
#pragma unroll
        for (int ks = 0; ks < 2; ks++) {
            unsigned ah[2][4], al[2][4];
#pragma unroll
            for (int mt = 0; mt < 2; mt++) {
                int row = wm * 32 + mt * 16;
                int c = ks * 8;
                ah[mt][0] = As[0][row + gq][c + tg];
                ah[mt][1] = As[0][row + gq + 8][c + tg];
                ah[mt][2] = As[0][row + gq][c + tg + 4];
                ah[mt][3] = As[0][row + gq + 8][c + tg + 4];
                al[mt][0] = As[1][row + gq][c + tg];
                al[mt][1] = As[1][row + gq + 8][c + tg];
                al[mt][2] = As[1][row + gq][c + tg + 4];
                al[mt][3] = As[1][row + gq + 8][c + tg + 4];
            }
#pragma unroll
            for (int nt = 0; nt < 8; nt++) {
                int col = wn * 64 + nt * 8 + gq;
                unsigned bh[2], bl[2];
                bh[0] = Bs[0][ks * 8 + tg][col];
                bh[1] = Bs[0][ks * 8 + tg + 4][col];
                bl[0] = Bs[1][ks * 8 + tg][col];
                bl[1] = Bs[1][ks * 8 + tg + 4][col];
#pragma unroll
                for (int mt = 0; mt < 2; mt++) {
                    mma_tf32(acc[mt][nt], ah[mt], bh);
                    mma_tf32(acc[mt][nt], ah[mt], bl);
                    mma_tf32(acc[mt][nt], al[mt], bh);
                }
            }
        }
        __syncthreads();
    }

#pragma unroll
    for (int mt = 0; mt < 2; mt++) {
#pragma unroll
        for (int nt = 0; nt < 8; nt++) {
            int row = bm * 128 + wm * 32 + mt * 16 + gq;
            int col = bn * 128 + wn * 64 + nt * 8 + tg * 2;
            float b0v = bias[col], b1v = bias[col + 1];
            g_Zpre[(size_t)row * G + col]     = acc[mt][nt][0] + b0v;
            g_Zpre[(size_t)row * G + col + 1] = acc[mt][nt][1] + b1v;
            g_Zpre[(size_t)(row + 8) * G + col]     = acc[mt][nt][2] + b0v;
            g_Zpre[(size_t)(row + 8) * G + col + 1] = acc[mt][nt][3] + b1v;
        }
    }
}

// ---------------- persistent recurrence, 3xTF32 ----------------
// 64 blocks x 256 threads. Block owns 16 hidden units (64 gate cols), M=64 batch,
// K=1024, K-chunk 32. Zs epilogue tile aliases Hs (dead after the k-loop).
__global__ __launch_bounds__(256) void lstm_persist(const float* __restrict__ Wh,
                                                    const int* __restrict__ lens,
                                                    int ymode,
                                                    float* __restrict__ yout) {
    __shared__ unsigned Hs[2][64][36];   // [hi/lo][b][k]   (18432 B)
    __shared__ unsigned Ws[2][32][68];   // [hi/lo][k][gatecol] (17408 B)
    __shared__ int     Ls[64];
    float (*Zs)[68] = reinterpret_cast<float(*)[68]>(&Hs[0][0][0]);  // 17408 B alias

    const int tid = threadIdx.x;
    const int wid = tid >> 5, lane = tid & 31;
    const int wm = wid & 3, wn = wid >> 2;
    const int gq = lane >> 2, tg = lane & 3;
    const int n0 = blockIdx.x * 16;

    if (tid < 64) Ls[tid] = read_len(lens, tid);
    __syncthreads();

    // loader indices
    const int hrow = tid >> 3;            // 0..31 (+32 second pass)
    const int hcol = (tid & 7) << 2;
    const int wkr = tid >> 4;             // 0..15 (+16 second pass)
    const int wcl = (tid & 15) << 2;      // 0..60, never crosses a gate-16 boundary
    const int wgate = wcl >> 4;
    const int wnn = wcl & 15;

    for (int t = 0; t < T; t++) {
        const float* __restrict__ h_in  = g_h[t & 1];
        float* __restrict__ h_out = g_h[(t + 1) & 1];
        const float* __restrict__ Zpre_t = g_Zpre + (size_t)t * B * G;

        float acc[4][4];
#pragma unroll
        for (int nt = 0; nt < 4; nt++)
#pragma unroll
            for (int q = 0; q < 4; q++) acc[nt][q] = 0.0f;

        for (int k0 = 0; k0 < 1024; k0 += 32) {
#pragma unroll
            for (int p = 0; p < 2; p++) {
                int rr = hrow + p * 32;
                float4 v = ldcg4(h_in + (size_t)rr * H + k0 + hcol);   // .cg: cross-block
                split_tf(v.x, Hs[0][rr][hcol + 0], Hs[1][rr][hcol + 0]);
                split_tf(v.y, Hs[0][rr][hcol + 1], Hs[1][rr][hcol + 1]);
                split_tf(v.z, Hs[0][rr][hcol + 2], Hs[1][rr][hcol + 2]);
                split_tf(v.w, Hs[0][rr][hcol + 3], Hs[1][rr][hcol + 3]);
            }
#pragma unroll
            for (int p = 0; p < 2; p++) {
                int kk = wkr + p * 16;
                int wc = wgate * H + n0 + wnn;
                float4 v = *(const float4*)(Wh + (size_t)(k0 + kk) * G + wc);
                split_tf(v.x, Ws[0][kk][wcl + 0], Ws[1][kk][wcl + 0]);
                split_tf(v.y, Ws[0][kk][wcl + 1], Ws[1][kk][wcl + 1]);
                split_tf(v.z, Ws[0][kk][wcl + 2], Ws[1][kk][wcl + 2]);
                split_tf(v.w, Ws[0][kk][wcl + 3], Ws[1][kk][wcl + 3]);
            }
            __syncthreads();
#pragma unroll
            for (int ks = 0; ks < 4; ks++) {
                unsigned ah[4], al[4];
                int row = wm * 16;
                int c = ks * 8;
                ah[0] = Hs[0][row + gq][c + tg];
                ah[1] = Hs[0][row + gq + 8][c + tg];
                ah[2] = Hs[0][row + gq][c + tg + 4];
                ah[3] = Hs[0][row + gq + 8][c + tg + 4];
                al[0] = Hs[1][row + gq][c + tg];
                al[1] = Hs[1][row + gq + 8][c + tg];
                al[2] = Hs[1][row + gq][c + tg + 4];
                al[3] = Hs[1][row + gq + 8][c + tg + 4];
#pragma unroll
                for (int nt = 0; nt < 4; nt++) {
                    int col = wn * 32 + nt * 8 + gq;
                    unsigned bh[2], bl[2];
                    bh[0] = Ws[0][ks * 8 + tg][col];
                    bh[1] = Ws[0][ks * 8 + tg + 4][col];
                    bl[0] = Ws[1][ks * 8 + tg][col];
                    bl[1] = Ws[1][ks * 8 + tg + 4][col];
                    mma_tf32(acc[nt], ah, bh);
                    mma_tf32(acc[nt], ah, bl);
                    mma_tf32(acc[nt], al, bh);
                }
            }
            __syncthreads();
        }

        // stash z tile (aliases Hs — dead after the final __syncthreads above)
#pragma unroll
        for (int nt = 0; nt < 4; nt++) {
            int row = wm * 16 + gq;
            int col = wn * 32 + nt * 8 + tg * 2;
            Zs[row][col]     = acc[nt][0];
            Zs[row][col + 1] = acc[nt][1];
            Zs[row + 8][col]     = acc[nt][2];
            Zs[row + 8][col + 1] = acc[nt][3];
        }
        __syncthreads();

        // fused gates + masking; 64 rows x 16 hidden units = 1024 items
        for (int it = tid; it < 64 * 16; it += 256) {
            int b = it >> 4;
            int nn = it & 15;
            int n = n0 + nn;
            size_t zb = (size_t)b * G;
            float zi = Zs[b][nn]      + Zpre_t[zb + 0 * H + n];
            float zj = Zs[b][16 + nn] + Zpre_t[zb + 1 * H + n];
            float zf = Zs[b][32 + nn] + Zpre_t[zb + 2 * H + n];
            float zo = Zs[b][48 + nn] + Zpre_t[zb + 3 * H + n];
            size_t hi = (size_t)b * H + n;
            bool m = t < Ls[b];
            float yv = 0.0f;
            if (m) {
                float cv = g_c[hi];                // block-private across the run
                float cn = cv * sigf(zf + 1.0f) + sigf(zi) * tanhf(zj);
                float hn = tanhf(cn) * sigf(zo);
                g_c[hi] = cn;
                h_out[hi] = hn;
                yv = hn;
            } else {
                h_out[hi] = __ldcg(h_in + hi);     // cross-block state: .cg
            }
            if (ymode == 0) {
                g_y0[((size_t)t * B + b) * H + n] = yv;
            } else {
                yout[((size_t)b * T + t) * H + n] = yv;
            }
        }

        grid_sync();
    }
}

// ---------------- final h/c copy ----------------
__global__ void copy_hc(float* __restrict__ out_h, float* __restrict__ out_c) {
    int i = blockIdx.x * 256 + threadIdx.x;
    if (i < B * H) { out_h[i] = g_h[0][i]; out_c[i] = g_c[i]; }
}

// ---------------- launch ----------------
extern "C" void kernel_launch(void* const* d_in, const int* in_sizes, int n_in,
                              void* d_out, int out_size) {
    // Size-based input identification (robust to metadata ordering):
    //   x: 64*512*1024 = 33554432   lengths: 64
    //   W0/W1: 2048*4096 = 8388608  b0/b1: 4096
    const float* x = nullptr;
    const int* lengths = nullptr;
    const float* W0 = nullptr; const float* b0 = nullptr;
    const float* W1 = nullptr; const float* b1 = nullptr;
    int wseen = 0, bseen = 0;
    for (int i = 0; i < n_in; i++) {
        long long s = in_sizes[i];
        if (s == (long long)B * T * D) x = (const float*)d_in[i];
        else if (s == B) lengths = (const int*)d_in[i];
        else if (s == (long long)(D + H) * G) {
            if (wseen++ == 0) W0 = (const float*)d_in[i];
            else W1 = (const float*)d_in[i];
        } else if (s == G) {
            if (bseen++ == 0) b0 = (const float*)d_in[i];
            else b1 = (const float*)d_in[i];
        }
    }

    float* out = (float*)d_out;
    float* out_y = out;
    float* out_h = out + (size_t)B * T * H;      // h_stack [2][B][H]
    float* out_c = out_h + 2 * B * H;            // c_stack [2][B][H]

    const int sgrid = (B * H + 255) / 256;
    dim3 ggrid(G / 128, (B * T) / 128);          // 32 x 256

    // ---- layer 0 ----
    init_state<<<sgrid, 256>>>();
    gemm_in<<<ggrid, 256>>>(x, W0, b0, 0);
    const float* Wh0 = W0 + (size_t)D * G;
    lstm_persist<<<PBLOCKS, 256>>>(Wh0, lengths, 0, nullptr);
    copy_hc<<<sgrid, 256>>>(out_h, out_c);

    // ---- layer 1 ----
    init_state<<<sgrid, 256>>>();
    gemm_in<<<ggrid, 256>>>(nullptr, W1, b1, 1);
    const float* Wh1 = W1 + (size_t)H * G;
    lstm_persist<<<PBLOCKS, 256>>>(Wh1, lengths, 1, out_y);
    copy_hc<<<sgrid, 256>>>(out_h + B * H, out_c + B * H);
}

// round 8
// speedup vs baseline: 1.2727x; 1.2727x over previous
#include <cuda_runtime.h>
#include <cstdint>

#define B 64
#define T 512
#define D 1024
#define H 1024
#define G 4096      // 4*H
#define PBLOCKS 128 // persistent grid size (<=148 SMs -> co-resident)

// ---------------- device scratch (no allocations allowed) ----------------
__device__ float g_Zpre[(size_t)T * B * G];   // [t][b][4H] pre-activations
__device__ float g_y0[(size_t)T * B * H];     // layer0 outputs [t][b][H]
__device__ float g_h[2][B * H];               // ping-pong hidden state (plain fp32)
__device__ float g_c[B * H];                  // cell state
// packed 3xTF32 operands: uint4 = {hi(k=8kg+tg), hi(8kg+tg+4), lo(...), lo(...)}
__device__ uint4 g_hsplit[2][128 * B * 4];    // [parity][(kg*64+row)*4+tg]
__device__ uint4 g_Wsplit[128 * G * 4];       // [(kg*4096+gcol)*4+tg], 32 MB
__device__ volatile int g_bar_count = 0;
__device__ volatile int g_bar_gen = 0;

// ---------------- helpers ----------------
__device__ __forceinline__ unsigned f2tf(float f) {
    unsigned u;
    asm("cvt.rna.tf32.f32 %0, %1;" : "=r"(u) : "f"(f));
    return u;
}

__device__ __forceinline__ void split_tf(float v, unsigned& hi, unsigned& lo) {
    hi = f2tf(v);
    lo = f2tf(v - __uint_as_float(hi));
}

__device__ __forceinline__ void mma_tf32(float c[4], const unsigned a[4], const unsigned b[2]) {
    asm volatile(
        "mma.sync.aligned.m16n8k8.row.col.f32.tf32.tf32.f32 "
        "{%0,%1,%2,%3}, {%4,%5,%6,%7}, {%8,%9}, {%0,%1,%2,%3};"
        : "+f"(c[0]), "+f"(c[1]), "+f"(c[2]), "+f"(c[3])
        : "r"(a[0]), "r"(a[1]), "r"(a[2]), "r"(a[3]), "r"(b[0]), "r"(b[1]));
}

__device__ __forceinline__ float sigf(float x) {
    return 1.0f / (1.0f + __expf(-x));
}

// Dtype-robust length read (harness passes int64; int32 also handled)
__device__ __forceinline__ int read_len(const int* p, int b) {
    int is64 = (p[1] == 0);
    return is64 ? p[2 * b] : p[b];
}

__device__ __forceinline__ void grid_sync() {
    __threadfence();
    __syncthreads();
    if (threadIdx.x == 0) {
        int gen = g_bar_gen;
        if (atomicAdd((int*)&g_bar_count, 1) == PBLOCKS - 1) {
            g_bar_count = 0;
            __threadfence();
            g_bar_gen = gen + 1;
        } else {
            while (g_bar_gen == gen) { __nanosleep(32); }
        }
        __threadfence();
    }
    __syncthreads();
}

// ---------------- init: zero h[0], c, packed h parity 0 ----------------
__global__ void init_state() {
    int i = blockIdx.x * 256 + threadIdx.x;
    if (i < B * H) { g_h[0][i] = 0.0f; g_c[i] = 0.0f; }
    if (i < 128 * B * 4) g_hsplit[0][i] = make_uint4(0, 0, 0, 0);
}

// ---------------- pre-split Wh into packed layout ----------------
// out[(kg*4096+gcol)*4+tg] = {hi(Wh[8kg+tg][gcol]), hi(Wh[8kg+tg+4][gcol]), lo, lo}
__global__ void split_W(const float* __restrict__ Wh) {
    int idx = blockIdx.x * 256 + threadIdx.x;   // 0 .. 128*4096*4-1
    int tg = idx & 3;
    int gcol = (idx >> 2) & 4095;
    int kg = idx >> 14;
    float v0 = Wh[(size_t)(8 * kg + tg) * G + gcol];
    float v1 = Wh[(size_t)(8 * kg + tg + 4) * G + gcol];
    unsigned h0, l0, h1, l1;
    split_tf(v0, h0, l0);
    split_tf(v1, h1, l1);
    g_Wsplit[idx] = make_uint4(h0, h1, l0, l1);
}

// ---------------- input GEMM, 3xTF32 (validated) ----------------
__global__ __launch_bounds__(256) void gemm_in(const float* __restrict__ Ax,
                                               const float* __restrict__ W,
                                               const float* __restrict__ bias,
                                               int mode) {
    __shared__ unsigned As[2][128][20];
    __shared__ unsigned Bs[2][16][132];

    const int bm = blockIdx.y, bn = blockIdx.x;
    const int tid = threadIdx.x;
    const int wid = tid >> 5, lane = tid & 31;
    const int wm = wid & 3, wn = wid >> 2;
    const int gq = lane >> 2, tg = lane & 3;

    const int arow_l = tid >> 2;
    const int acol = (tid & 3) << 2;
    const float* arp[2];
#pragma unroll
    for (int p = 0; p < 2; p++) {
        int r = bm * 128 + arow_l + p * 64;
        arp[p] = (mode == 0) ? (Ax + ((size_t)(r & (B - 1)) * T + (r >> 6)) * D)
                             : (g_y0 + (size_t)r * H);
    }
    const int brow_l = tid >> 5;
    const int bcol = lane << 2;

    float acc[2][8][4];
#pragma unroll
    for (int mt = 0; mt < 2; mt++)
#pragma unroll
        for (int nt = 0; nt < 8; nt++)
#pragma unroll
            for (int q = 0; q < 4; q++) acc[mt][nt][q] = 0.0f;

    for (int k0 = 0; k0 < 1024; k0 += 16) {
#pragma unroll
        for (int p = 0; p < 2; p++) {
            float4 v = *(const float4*)(arp[p] + k0 + acol);
            int rr = arow_l + p * 64;
            split_tf(v.x, As[0][rr][acol + 0], As[1][rr][acol + 0]);
            split_tf(v.y, As[0][rr][acol + 1], As[1][rr][acol + 1]);
            split_tf(v.z, As[0][rr][acol + 2], As[1][rr][acol + 2]);
            split_tf(v.w, As[0][rr][acol + 3], As[1][rr][acol + 3]);
        }
#pragma unroll
        for (int p = 0; p < 2; p++) {
            int kk = brow_l + p * 8;
            float4 v = *(const float4*)(W + (size_t)(k0 + kk) * G + bn * 128 + bcol);
            split_tf(v.x, Bs[0][kk][bcol + 0], Bs[1][kk][bcol + 0]);
            split_tf(v.y, Bs[0][kk][bcol + 1], Bs[1][kk][bcol + 1]);
            split_tf(v.z, Bs[0][kk][bcol + 2], Bs[1][kk][bcol + 2]);
            split_tf(v.w, Bs[0][kk][bcol + 3], Bs[1][kk][bcol + 3]);
        }
        __syncthreads();
#pragma unroll
        for (int ks = 0; ks < 2; ks++) {
            unsigned ah[2][4], al[2][4];
#pragma unroll
            for (int mt = 0; mt < 2; mt++) {
                int row = wm * 32 + mt * 16;
                int c = ks * 8;
                ah[mt][0] = As[0][row + gq][c + tg];
                ah[mt][1] = As[0][row + gq + 8][c + tg];
                ah[mt][2] = As[0][row + gq][c + tg + 4];
                ah[mt][3] = As[0][row + gq + 8][c + tg + 4];
                al[mt][0] = As[1][row + gq][c + tg];
                al[mt][1] = As[1][row + gq + 8][c + tg];
                al[mt][2] = As[1][row + gq][c + tg + 4];
                al[mt][3] = As[1][row + gq + 8][c + tg + 4];
            }
#pragma unroll
            for (int nt = 0; nt < 8; nt++) {
                int col = wn * 64 + nt * 8 + gq;
                unsigned bh[2], bl[2];
                bh[0] = Bs[0][ks * 8 + tg][col];
                bh[1] = Bs[0][ks * 8 + tg + 4][col];
                bl[0] = Bs[1][ks * 8 + tg][col];
                bl[1] = Bs[1][ks * 8 + tg + 4][col];
#pragma unroll
                for (int mt = 0; mt < 2; mt++) {
                    mma_tf32(acc[mt][nt], ah[mt], bh);
                    mma_tf32(acc[mt][nt], ah[mt], bl);
                    mma_tf32(acc[mt][nt], al[mt], bh);
                }
            }
        }
        __syncthreads();
    }

#pragma unroll
    for (int mt = 0; mt < 2; mt++) {
#pragma unroll
        for (int nt = 0; nt < 8; nt++) {
            int row = bm * 128 + wm * 32 + mt * 16 + gq;
            int col = bn * 128 + wn * 64 + nt * 8 + tg * 2;
            float b0v = bias[col], b1v = bias[col + 1];
            g_Zpre[(size_t)row * G + col]     = acc[mt][nt][0] + b0v;
            g_Zpre[(size_t)row * G + col + 1] = acc[mt][nt][1] + b1v;
            g_Zpre[(size_t)(row + 8) * G + col]     = acc[mt][nt][2] + b0v;
            g_Zpre[(size_t)(row + 8) * G + col + 1] = acc[mt][nt][3] + b1v;
        }
    }
}

// ---------------- persistent recurrence v2 ----------------
// 128 blocks x 256 threads. Block owns 8 hidden units (32 gate cols).
// Fragments loaded DIRECTLY from packed L2 buffers (no smem staging, no
// k-loop syncs). 8 warps = 4(M) x 2(N); warp tile 16 x 16.
__global__ __launch_bounds__(256) void lstm_persist(const int* __restrict__ lens,
                                                    int ymode,
                                                    float* __restrict__ yout) {
    __shared__ float Zs[64][36];
    __shared__ int   Ls[64];

    const int tid = threadIdx.x;
    const int wid = tid >> 5, lane = tid & 31;
    const int wm = wid & 3, wn = wid >> 2;
    const int gq = lane >> 2, tg = lane & 3;
    const int n0 = blockIdx.x * 8;

    if (tid < 64) Ls[tid] = read_len(lens, tid);
    __syncthreads();

    // per-lane constant offsets
    const int row0 = wm * 16;
    const int aoff0 = (row0 + gq) * 4 + tg;        // + kg*256
    const int aoff1 = (row0 + gq + 8) * 4 + tg;
    int gcol[2];
#pragma unroll
    for (int nt = 0; nt < 2; nt++) {
        int c = wn * 16 + nt * 8 + gq;             // local col 0..31
        gcol[nt] = ((c >> 3) * H + n0 + (c & 7)) * 4 + tg;  // + kg*16384
    }

    for (int t = 0; t < T; t++) {
        const float* __restrict__ h_in  = g_h[t & 1];
        float* __restrict__ h_out = g_h[(t + 1) & 1];
        const uint4* __restrict__ Ah = g_hsplit[t & 1];
        uint4* __restrict__ Aout = g_hsplit[(t + 1) & 1];
        const float* __restrict__ Zpre_t = g_Zpre + (size_t)t * B * G;

        float accA[2][4], accB[2][4];
#pragma unroll
        for (int nt = 0; nt < 2; nt++)
#pragma unroll
            for (int q = 0; q < 4; q++) { accA[nt][q] = 0.0f; accB[nt][q] = 0.0f; }

#pragma unroll 4
        for (int kg = 0; kg < 128; kg++) {
            uint4 a0 = __ldcg(Ah + kg * 256 + aoff0);   // cross-block state: .cg
            uint4 a1 = __ldcg(Ah + kg * 256 + aoff1);
            unsigned ah[4] = {a0.x, a1.x, a0.y, a1.y};
            unsigned al[4] = {a0.z, a1.z, a0.w, a1.w};
#pragma unroll
            for (int nt = 0; nt < 2; nt++) {
                uint4 bv = __ldg(g_Wsplit + kg * 16384 + gcol[nt]);
                unsigned bh[2] = {bv.x, bv.y};
                unsigned bl[2] = {bv.z, bv.w};
                mma_tf32(accA[nt], ah, bh);
                mma_tf32(accB[nt], ah, bl);
                mma_tf32(accA[nt], al, bh);
            }
        }

        // stash z tile (accA+accB) for gate regrouping
#pragma unroll
        for (int nt = 0; nt < 2; nt++) {
            int row = wm * 16 + gq;
            int col = wn * 16 + nt * 8 + tg * 2;
            Zs[row][col]     = accA[nt][0] + accB[nt][0];
            Zs[row][col + 1] = accA[nt][1] + accB[nt][1];
            Zs[row + 8][col]     = accA[nt][2] + accB[nt][2];
            Zs[row + 8][col + 1] = accA[nt][3] + accB[nt][3];
        }
        __syncthreads();

        // fused gates + masking; 64 batch x 8 units = 512 items, 2 per thread
#pragma unroll
        for (int p = 0; p < 2; p++) {
            int it = tid + p * 256;
            int b = it >> 3;
            int nn = it & 7;
            int n = n0 + nn;
            size_t zb = (size_t)b * G;
            float zi = Zs[b][0 * 8 + nn] + Zpre_t[zb + 0 * H + n];
            float zj = Zs[b][1 * 8 + nn] + Zpre_t[zb + 1 * H + n];
            float zf = Zs[b][2 * 8 + nn] + Zpre_t[zb + 2 * H + n];
            float zo = Zs[b][3 * 8 + nn] + Zpre_t[zb + 3 * H + n];
            size_t hi = (size_t)b * H + n;
            bool m = t < Ls[b];
            float yv = 0.0f;
            float newh;
            if (m) {
                float cv = g_c[hi];                // block-private across the run
                float cn = cv * sigf(zf + 1.0f) + sigf(zi) * tanhf(zj);
                newh = tanhf(cn) * sigf(zo);
                g_c[hi] = cn;
                yv = newh;
            } else {
                newh = __ldcg(h_in + hi);          // hold state (cross-block: .cg)
            }
            h_out[hi] = newh;
            // packed split write for next step's A-fragments
            {
                int kg = n >> 3;                   // == blockIdx.x
                int k7 = n & 7;
                int tg2 = k7 & 3;
                int hw = k7 >> 2;                  // 0 or 1
                unsigned hu, lu;
                split_tf(newh, hu, lu);
                float* df = (float*)(Aout + (kg * 64 + b) * 4 + tg2);
                df[hw]     = __uint_as_float(hu);
                df[2 + hw] = __uint_as_float(lu);
            }
            if (ymode == 0) {
                g_y0[((size_t)t * B + b) * H + n] = yv;
            } else {
                yout[((size_t)b * T + t) * H + n] = yv;
            }
        }

        grid_sync();
    }
}

// ---------------- final h/c copy ----------------
__global__ void copy_hc(float* __restrict__ out_h, float* __restrict__ out_c) {
    int i = blockIdx.x * 256 + threadIdx.x;
    if (i < B * H) { out_h[i] = g_h[0][i]; out_c[i] = g_c[i]; }
}

// ---------------- launch ----------------
extern "C" void kernel_launch(void* const* d_in, const int* in_sizes, int n_in,
                              void* d_out, int out_size) {
    // size-based input identification
    const float* x = nullptr;
    const int* lengths = nullptr;
    const float* W0 = nullptr; const float* b0 = nullptr;
    const float* W1 = nullptr; const float* b1 = nullptr;
    int wseen = 0, bseen = 0;
    for (int i = 0; i < n_in; i++) {
        long long s = in_sizes[i];
        if (s == (long long)B * T * D) x = (const float*)d_in[i];
        else if (s == B) lengths = (const int*)d_in[i];
        else if (s == (long long)(D + H) * G) {
            if (wseen++ == 0) W0 = (const float*)d_in[i];
            else W1 = (const float*)d_in[i];
        } else if (s == G) {
            if (bseen++ == 0) b0 = (const float*)d_in[i];
            else b1 = (const float*)d_in[i];
        }
    }

    float* out = (float*)d_out;
    float* out_y = out;
    float* out_h = out + (size_t)B * T * H;      // h_stack [2][B][H]
    float* out_c = out_h + 2 * B * H;            // c_stack [2][B][H]

    const int sgrid = (B * H + 255) / 256;
    dim3 ggrid(G / 128, (B * T) / 128);          // 32 x 256
    const int wgrid = (128 * G * 4) / 256;       // split_W blocks

    // ---- layer 0 ----
    init_state<<<sgrid, 256>>>();
    split_W<<<wgrid, 256>>>(W0 + (size_t)D * G);
    gemm_in<<<ggrid, 256>>>(x, W0, b0, 0);
    lstm_persist<<<PBLOCKS, 256>>>(lengths, 0, nullptr);
    copy_hc<<<sgrid, 256>>>(out_h, out_c);

    // ---- layer 1 ----
    init_state<<<sgrid, 256>>>();
    split_W<<<wgrid, 256>>>(W1 + (size_t)H * G);
    gemm_in<<<ggrid, 256>>>(nullptr, W1, b1, 1);
    lstm_persist<<<PBLOCKS, 256>>>(lengths, 1, out_y);
    copy_hc<<<sgrid, 256>>>(out_h + B * H, out_c + B * H);
}

// round 10
// speedup vs baseline: 2.2320x; 1.7538x over previous
#include <cuda_runtime.h>
#include <cuda_bf16.h>
#include <cstdint>

#define B 64
#define T 512
#define D 1024
#define H 1024
#define G 4096      // 4*H
#define PBLOCKS 128 // persistent grid size (<=148 SMs -> co-resident)

// ---------------- device scratch (no allocations allowed) ----------------
__device__ float g_Zpre[(size_t)T * B * G];   // [t][b][4H] pre-activations
__device__ float g_y0[(size_t)T * B * H];     // layer0 outputs [t][b][H]
__device__ float g_h[2][B * H];               // ping-pong hidden state (plain fp32)
__device__ float g_c[B * H];                  // cell state
// packed 3xBF16 operands (bf16x2 pairs over k):
// A (h):  [parity][(kg*64 + row)*4 + tg] = {hiP0, hiP1, loP0, loP1}
//         P0 = k(2tg,2tg+1), P1 = k(2tg+8,2tg+9), kg = 16-k group (0..63)
__device__ uint4 g_hsplit[2][64 * B * 4];
// W:      [(kg*4096 + gcol)*4 + tg] same pair layout, 16 MB
__device__ uint4 g_Wsplit[64 * G * 4];
__device__ volatile int g_bar_count = 0;
__device__ volatile int g_bar_gen = 0;

// ---------------- helpers ----------------
__device__ __forceinline__ void split_bf(float v, unsigned short& h, unsigned short& l) {
    __nv_bfloat16 hb = __float2bfloat16_rn(v);
    float r = v - __bfloat162float(hb);
    __nv_bfloat16 lb = __float2bfloat16_rn(r);
    h = *(unsigned short*)&hb;
    l = *(unsigned short*)&lb;
}

__device__ __forceinline__ unsigned pack2(unsigned short a, unsigned short b) {
    return (unsigned)a | ((unsigned)b << 16);
}

// m16n8k16 bf16 mma, fp32 accum
__device__ __forceinline__ void mma_bf16(float c[4], const unsigned a[4], const unsigned b[2]) {
    asm volatile(
        "mma.sync.aligned.m16n8k16.row.col.f32.bf16.bf16.f32 "
        "{%0,%1,%2,%3}, {%4,%5,%6,%7}, {%8,%9}, {%0,%1,%2,%3};"
        : "+f"(c[0]), "+f"(c[1]), "+f"(c[2]), "+f"(c[3])
        : "r"(a[0]), "r"(a[1]), "r"(a[2]), "r"(a[3]), "r"(b[0]), "r"(b[1]));
}

__device__ __forceinline__ float sigf(float x) {
    return 1.0f / (1.0f + __expf(-x));
}

__device__ __forceinline__ int read_len(const int* p, int b) {
    int is64 = (p[1] == 0);
    return is64 ? p[2 * b] : p[b];
}

__device__ __forceinline__ void grid_sync() {
    __threadfence();
    __syncthreads();
    if (threadIdx.x == 0) {
        int gen = g_bar_gen;
        if (atomicAdd((int*)&g_bar_count, 1) == PBLOCKS - 1) {
            g_bar_count = 0;
            __threadfence();
            g_bar_gen = gen + 1;
        } else {
            while (g_bar_gen == gen) { __nanosleep(32); }
        }
        __threadfence();
    }
    __syncthreads();
}

// ---------------- init ----------------
__global__ void init_state() {
    int i = blockIdx.x * 256 + threadIdx.x;
    if (i < B * H) { g_h[0][i] = 0.0f; g_c[i] = 0.0f; }
    if (i < 64 * B * 4) g_hsplit[0][i] = make_uint4(0, 0, 0, 0);
}

// ---------------- pre-split Wh into packed bf16 layout ----------------
__global__ void split_W(const float* __restrict__ Wh) {
    int idx = blockIdx.x * 256 + threadIdx.x;   // 0 .. 64*4096*4-1
    int tg = idx & 3;
    int gcol = (idx >> 2) & 4095;
    int kg = idx >> 14;
    int k0 = 16 * kg + 2 * tg;
    float v00 = Wh[(size_t)(k0) * G + gcol];
    float v01 = Wh[(size_t)(k0 + 1) * G + gcol];
    float v10 = Wh[(size_t)(k0 + 8) * G + gcol];
    float v11 = Wh[(size_t)(k0 + 9) * G + gcol];
    unsigned short h00, l00, h01, l01, h10, l10, h11, l11;
    split_bf(v00, h00, l00);
    split_bf(v01, h01, l01);
    split_bf(v10, h10, l10);
    split_bf(v11, h11, l11);
    g_Wsplit[idx] = make_uint4(pack2(h00, h01), pack2(h10, h11),
                               pack2(l00, l01), pack2(l10, l11));
}

// ---------------- input GEMM, 3xBF16 ----------------
// M=32768, N=4096, K=1024. Tile 128x128, K-chunk 32.
// 256 threads = 8 warps (4M x 2N), warp tile 32x64.
__global__ __launch_bounds__(256) void gemm_in(const float* __restrict__ Ax,
                                               const float* __restrict__ W,
                                               const float* __restrict__ bias,
                                               int mode) {
    __shared__ unsigned As[2][128][18];   // [hi/lo][row][kpair 0..15]
    __shared__ unsigned Bs[2][128][18];   // [hi/lo][ncol][kpair 0..15]

    const int bm = blockIdx.y, bn = blockIdx.x;
    const int tid = threadIdx.x;
    const int wid = tid >> 5, lane = tid & 31;
    const int wm = wid & 3, wn = wid >> 2;
    const int gq = lane >> 2, tg = lane & 3;

    // A loader: 128 rows x 32 k; thread: row (tid>>3)+32p, k4 = (tid&7)*4
    const int arow_l = tid >> 3;
    const int ak4 = (tid & 7) << 2;
    const float* arp[4];
#pragma unroll
    for (int p = 0; p < 4; p++) {
        int r = bm * 128 + arow_l + p * 32;
        arp[p] = (mode == 0) ? (Ax + ((size_t)(r & (B - 1)) * T + (r >> 6)) * D)
                             : (g_y0 + (size_t)r * H);
    }
    // B loader: kp = tid>>4 (0..15 -> k = 2kp,2kp+1), nq = (tid&15)*8
    const int bkp = tid >> 4;
    const int bnq = (tid & 15) << 3;

    float acc[2][8][4];
#pragma unroll
    for (int mt = 0; mt < 2; mt++)
#pragma unroll
        for (int nt = 0; nt < 8; nt++)
#pragma unroll
            for (int q = 0; q < 4; q++) acc[mt][nt][q] = 0.0f;

    for (int k0 = 0; k0 < 1024; k0 += 32) {
        // A chunk
#pragma unroll
        for (int p = 0; p < 4; p++) {
            float4 v = *(const float4*)(arp[p] + k0 + ak4);
            int rr = arow_l + p * 32;
            unsigned short hx, lx, hy, ly, hz, lz, hw, lw;
            split_bf(v.x, hx, lx); split_bf(v.y, hy, ly);
            split_bf(v.z, hz, lz); split_bf(v.w, hw, lw);
            As[0][rr][(ak4 >> 1) + 0] = pack2(hx, hy);
            As[0][rr][(ak4 >> 1) + 1] = pack2(hz, hw);
            As[1][rr][(ak4 >> 1) + 0] = pack2(lx, ly);
            As[1][rr][(ak4 >> 1) + 1] = pack2(lz, lw);
        }
        // B chunk (transpose + pair-pack on store)
#pragma unroll
        for (int j2 = 0; j2 < 2; j2++) {
            const float* wp = W + (size_t)(k0 + 2 * bkp) * G + bn * 128 + bnq + j2 * 4;
            float4 v0 = *(const float4*)(wp);
            float4 v1 = *(const float4*)(wp + G);
            unsigned short h0, l0, h1, l1;
#pragma unroll
            for (int j = 0; j < 4; j++) {
                float e0 = (&v0.x)[j], e1 = (&v1.x)[j];
                split_bf(e0, h0, l0);
                split_bf(e1, h1, l1);
                Bs[0][bnq + j2 * 4 + j][bkp] = pack2(h0, h1);
                Bs[1][bnq + j2 * 4 + j][bkp] = pack2(l0, l1);
            }
        }
        __syncthreads();
#pragma unroll
        for (int ks = 0; ks < 2; ks++) {
            unsigned ah[2][4], al[2][4];
#pragma unroll
            for (int mt = 0; mt < 2; mt++) {
                int row = wm * 32 + mt * 16;
                int c = ks * 8;
                ah[mt][0] = As[0][row + gq][c + tg];
                ah[mt][1] = As[0][row + gq + 8][c + tg];
                ah[mt][2] = As[0][row + gq][c + tg + 4];
                ah[mt][3] = As[0][row + gq + 8][c + tg + 4];
                al[mt][0] = As[1][row + gq][c + tg];
                al[mt][1] = As[1][row + gq + 8][c + tg];
                al[mt][2] = As[1][row + gq][c + tg + 4];
                al[mt][3] = As[1][row + gq + 8][c + tg + 4];
            }
#pragma unroll
            for (int nt = 0; nt < 8; nt++) {
                int col = wn * 64 + nt * 8 + gq;
                unsigned bh[2], bl[2];
                bh[0] = Bs[0][col][ks * 8 + tg];
                bh[1] = Bs[0][col][ks * 8 + tg + 4];
                bl[0] = Bs[1][col][ks * 8 + tg];
                bl[1] = Bs[1][col][ks * 8 + tg + 4];
#pragma unroll
                for (int mt = 0; mt < 2; mt++) {
                    mma_bf16(acc[mt][nt], ah[mt], bh);
                    mma_bf16(acc[mt][nt], ah[mt], bl);
                    mma_bf16(acc[mt][nt], al[mt], bh);
                }
            }
        }
        __syncthreads();
    }

#pragma unroll
    for (int mt = 0; mt < 2; mt++) {
#pragma unroll
        for (int nt = 0; nt < 8; nt++) {
            int row = bm * 128 + wm * 32 + mt * 16 + gq;
            int col = bn * 128 + wn * 64 + nt * 8 + tg * 2;
            float b0v = bias[col], b1v = bias[col + 1];
            g_Zpre[(size_t)row * G + col]     = acc[mt][nt][0] + b0v;
            g_Zpre[(size_t)row * G + col + 1] = acc[mt][nt][1] + b1v;
            g_Zpre[(size_t)(row + 8) * G + col]     = acc[mt][nt][2] + b0v;
            g_Zpre[(size_t)(row + 8) * G + col + 1] = acc[mt][nt][3] + b1v;
        }
    }
}

// ---------------- persistent recurrence, 3xBF16 ----------------
// 128 blocks x 256 threads. Block owns 8 hidden units (32 gate cols).
// Fragments direct from packed L2 buffers; no k-loop syncs.
__global__ __launch_bounds__(256) void lstm_persist(const int* __restrict__ lens,
                                                    int ymode,
                                                    float* __restrict__ yout) {
    __shared__ float Zs[64][36];
    __shared__ int   Ls[64];

    const int tid = threadIdx.x;
    const int wid = tid >> 5;
    const int lane = tid & 31;
    const int wm = wid & 3, wn = wid >> 2;
    const int gq = lane >> 2, tg = lane & 3;
    const int n0 = blockIdx.x * 8;

    if (tid < 64) Ls[tid] = read_len(lens, tid);
    __syncthreads();

    const int row0 = wm * 16;
    const int aoff0 = (row0 + gq) * 4 + tg;        // + kg*256
    const int aoff1 = (row0 + gq + 8) * 4 + tg;
    int gcol[2];
#pragma unroll
    for (int nt = 0; nt < 2; nt++) {
        int c = wn * 16 + nt * 8 + gq;             // local col 0..31
        gcol[nt] = ((c >> 3) * H + n0 + (c & 7)) * 4 + tg;  // + kg*16384
    }

    for (int t = 0; t < T; t++) {
        const float* __restrict__ h_in  = g_h[t & 1];
        float* __restrict__ h_out = g_h[(t + 1) & 1];
        const uint4* __restrict__ Ah = g_hsplit[t & 1];
        uint4* __restrict__ Aout = g_hsplit[(t + 1) & 1];
        const float* __restrict__ Zpre_t = g_Zpre + (size_t)t * B * G;

        float accA[2][4], accB[2][4];
#pragma unroll
        for (int nt = 0; nt < 2; nt++)
#pragma unroll
            for (int q = 0; q < 4; q++) { accA[nt][q] = 0.0f; accB[nt][q] = 0.0f; }

        uint4 a0 = __ldcg(Ah + aoff0);
        uint4 a1 = __ldcg(Ah + aoff1);
#pragma unroll 4
        for (int kg = 0; kg < 64; kg++) {
            uint4 na0, na1;
            if (kg < 63) {
                na0 = __ldcg(Ah + (kg + 1) * 256 + aoff0);
                na1 = __ldcg(Ah + (kg + 1) * 256 + aoff1);
            }
            unsigned ah[4] = {a0.x, a1.x, a0.y, a1.y};
            unsigned al[4] = {a0.z, a1.z, a0.w, a1.w};
#pragma unroll
            for (int nt = 0; nt < 2; nt++) {
                uint4 bv = __ldg(g_Wsplit + kg * 16384 + gcol[nt]);
                unsigned bh[2] = {bv.x, bv.y};
                unsigned bl[2] = {bv.z, bv.w};
                mma_bf16(accA[nt], ah, bh);
                mma_bf16(accB[nt], ah, bl);
                mma_bf16(accA[nt], al, bh);
            }
            a0 = na0; a1 = na1;
        }

#pragma unroll
        for (int nt = 0; nt < 2; nt++) {
            int row = wm * 16 + gq;
            int col = wn * 16 + nt * 8 + tg * 2;
            Zs[row][col]     = accA[nt][0] + accB[nt][0];
            Zs[row][col + 1] = accA[nt][1] + accB[nt][1];
            Zs[row + 8][col]     = accA[nt][2] + accB[nt][2];
            Zs[row + 8][col + 1] = accA[nt][3] + accB[nt][3];
        }
        __syncthreads();

#pragma unroll
        for (int p = 0; p < 2; p++) {
            int it = tid + p * 256;
            int b = it >> 3;
            int nn = it & 7;
            int n = n0 + nn;
            size_t zb = (size_t)b * G;
            float zi = Zs[b][0 * 8 + nn] + Zpre_t[zb + 0 * H + n];
            float zj = Zs[b][1 * 8 + nn] + Zpre_t[zb + 1 * H + n];
            float zf = Zs[b][2 * 8 + nn] + Zpre_t[zb + 2 * H + n];
            float zo = Zs[b][3 * 8 + nn] + Zpre_t[zb + 3 * H + n];
            size_t hi = (size_t)b * H + n;
            bool m = t < Ls[b];
            float yv = 0.0f;
            float newh;
            if (m) {
                float cv = g_c[hi];
                float cn = cv * sigf(zf + 1.0f) + sigf(zi) * tanhf(zj);
                newh = tanhf(cn) * sigf(zo);
                g_c[hi] = cn;
                yv = newh;
            } else {
                newh = __ldcg(h_in + hi);
            }
            h_out[hi] = newh;
            // packed bf16 split write for next step's A-fragments
            {
                int kg = n >> 4;
                int k15 = n & 15;
                int tg2 = (k15 & 7) >> 1;
                int cbit = k15 & 1;        // element within pair
                int w = k15 >> 3;          // pair0 / pair1
                unsigned short hu, lu;
                split_bf(newh, hu, lu);
                unsigned short* base = (unsigned short*)(Aout + (kg * 64 + b) * 4 + tg2);
                base[w * 2 + cbit]     = hu;   // words x/y
                base[4 + w * 2 + cbit] = lu;   // words z/w
            }
            if (ymode == 0) {
                g_y0[((size_t)t * B + b) * H + n] = yv;
            } else {
                yout[((size_t)b * T + t) * H + n] = yv;
            }
        }

        grid_sync();
    }
}

// ---------------- final h/c copy ----------------
__global__ void copy_hc(float* __restrict__ out_h, float* __restrict__ out_c) {
    int i = blockIdx.x * 256 + threadIdx.x;
    if (i < B * H) { out_h[i] = g_h[0][i]; out_c[i] = g_c[i]; }
}

// ---------------- launch ----------------
extern "C" void kernel_launch(void* const* d_in, const int* in_sizes, int n_in,
                              void* d_out, int out_size) {
    const float* x = nullptr;
    const int* lengths = nullptr;
    const float* W0 = nullptr; const float* b0 = nullptr;
    const float* W1 = nullptr; const float* b1 = nullptr;
    int wseen = 0, bseen = 0;
    for (int i = 0; i < n_in; i++) {
        long long s = in_sizes[i];
        if (s == (long long)B * T * D) x = (const float*)d_in[i];
        else if (s == B) lengths = (const int*)d_in[i];
        else if (s == (long long)(D + H) * G) {
            if (wseen++ == 0) W0 = (const float*)d_in[i];
            else W1 = (const float*)d_in[i];
        } else if (s == G) {
            if (bseen++ == 0) b0 = (const float*)d_in[i];
            else b1 = (const float*)d_in[i];
        }
    }

    float* out = (float*)d_out;
    float* out_y = out;
    float* out_h = out + (size_t)B * T * H;      // h_stack [2][B][H]
    float* out_c = out_h + 2 * B * H;            // c_stack [2][B][H]

    const int sgrid = (B * H + 255) / 256;
    dim3 ggrid(G / 128, (B * T) / 128);          // 32 x 256
    const int wgrid = (64 * G * 4) / 256;        // split_W blocks

    // ---- layer 0 ----
    init_state<<<sgrid, 256>>>();
    split_W<<<wgrid, 256>>>(W0 + (size_t)D * G);
    gemm_in<<<ggrid, 256>>>(x, W0, b0, 0);
    lstm_persist<<<PBLOCKS, 256>>>(lengths, 0, nullptr);
    copy_hc<<<sgrid, 256>>>(out_h, out_c);

    // ---- layer 1 ----
    init_state<<<sgrid, 256>>>();
    split_W<<<wgrid, 256>>>(W1 + (size_t)H * G);
    gemm_in<<<ggrid, 256>>>(nullptr, W1, b1, 1);
    lstm_persist<<<PBLOCKS, 256>>>(lengths, 1, out_y);
    copy_hc<<<sgrid, 256>>>(out_h + B * H, out_c + B * H);
}

// round 11
// speedup vs baseline: 3.3400x; 1.4964x over previous
#include <cuda_runtime.h>
#include <cuda_bf16.h>
#include <cstdint>

#define B 64
#define T 512
#define D 1024
#define H 1024
#define G 4096      // 4*H
#define PBLOCKS 128 // persistent grid size (<=148 SMs -> co-resident)

// ---------------- device scratch (no allocations allowed) ----------------
__device__ float g_Zpre[(size_t)T * B * G];        // [t][b][4H] pre-activations
__device__ float g_h[2][B * H];                    // ping-pong hidden state (fp32)
__device__ float g_c[B * H];                       // cell state
// packed bf16x2 planes for the input GEMM:
//   Apack[plane][r*512 + kp] = pack2(v(2kp), v(2kp+1)), r = t*B + b
__device__ unsigned g_Apack[2][(size_t)B * T * 512];   // 134 MB
//   Wpack[plane][col*512 + kp] = pack2(W[2kp][col], W[2kp+1][col])
__device__ unsigned g_Wpack[2][(size_t)G * 512];       // 16 MB
// packed operands for the recurrence (validated round-10 layout):
__device__ uint4 g_hsplit[2][64 * B * 4];
__device__ uint4 g_Wsplit[64 * G * 4];                 // 16 MB
__device__ volatile int g_bar_count = 0;
__device__ volatile int g_bar_gen = 0;

// ---------------- helpers ----------------
__device__ __forceinline__ void split_bf(float v, unsigned short& h, unsigned short& l) {
    __nv_bfloat16 hb = __float2bfloat16_rn(v);
    float r = v - __bfloat162float(hb);
    __nv_bfloat16 lb = __float2bfloat16_rn(r);
    h = *(unsigned short*)&hb;
    l = *(unsigned short*)&lb;
}

__device__ __forceinline__ unsigned pack2(unsigned short a, unsigned short b) {
    return (unsigned)a | ((unsigned)b << 16);
}

__device__ __forceinline__ void mma_bf16(float c[4], const unsigned a[4], const unsigned b[2]) {
    asm volatile(
        "mma.sync.aligned.m16n8k16.row.col.f32.bf16.bf16.f32 "
        "{%0,%1,%2,%3}, {%4,%5,%6,%7}, {%8,%9}, {%0,%1,%2,%3};"
        : "+f"(c[0]), "+f"(c[1]), "+f"(c[2]), "+f"(c[3])
        : "r"(a[0]), "r"(a[1]), "r"(a[2]), "r"(a[3]), "r"(b[0]), "r"(b[1]));
}

__device__ __forceinline__ float sigf(float x) {
    return 1.0f / (1.0f + __expf(-x));
}

__device__ __forceinline__ int read_len(const int* p, int b) {
    int is64 = (p[1] == 0);
    return is64 ? p[2 * b] : p[b];
}

__device__ __forceinline__ void grid_sync() {
    __threadfence();
    __syncthreads();
    if (threadIdx.x == 0) {
        int gen = g_bar_gen;
        if (atomicAdd((int*)&g_bar_count, 1) == PBLOCKS - 1) {
            g_bar_count = 0;
            __threadfence();
            g_bar_gen = gen + 1;
        } else {
            while (g_bar_gen == gen) { __nanosleep(32); }
        }
        __threadfence();
    }
    __syncthreads();
}

// ---------------- init ----------------
__global__ void init_state() {
    int i = blockIdx.x * 256 + threadIdx.x;
    if (i < B * H) { g_h[0][i] = 0.0f; g_c[i] = 0.0f; }
    if (i < 64 * B * 4) g_hsplit[0][i] = make_uint4(0, 0, 0, 0);
}

// ---------------- pre-split x into Apack ----------------
__global__ void split_x(const float* __restrict__ x) {
    size_t idx = (size_t)blockIdx.x * 256 + threadIdx.x;   // over B*T*512
    int kp = (int)(idx & 511);
    size_t r = idx >> 9;
    int b = (int)(r & 63);
    int t = (int)(r >> 6);
    float2 v = *(const float2*)(x + ((size_t)b * T + t) * D + 2 * kp);
    unsigned short h0, l0, h1, l1;
    split_bf(v.x, h0, l0);
    split_bf(v.y, h1, l1);
    g_Apack[0][idx] = pack2(h0, h1);
    g_Apack[1][idx] = pack2(l0, l1);
}

// ---------------- pre-split input-part of W into Wpack ----------------
__global__ void split_Win(const float* __restrict__ W) {
    size_t idx = (size_t)blockIdx.x * 256 + threadIdx.x;   // over G*512
    int col = (int)(idx & 4095);
    int kp = (int)(idx >> 12);
    float v0 = W[(size_t)(2 * kp) * G + col];
    float v1 = W[(size_t)(2 * kp + 1) * G + col];
    unsigned short h0, l0, h1, l1;
    split_bf(v0, h0, l0);
    split_bf(v1, h1, l1);
    g_Wpack[0][(size_t)col * 512 + kp] = pack2(h0, h1);
    g_Wpack[1][(size_t)col * 512 + kp] = pack2(l0, l1);
}

// ---------------- pre-split recurrent Wh (round-10 layout, validated) ----------------
__global__ void split_W(const float* __restrict__ Wh) {
    int idx = blockIdx.x * 256 + threadIdx.x;   // 0 .. 64*4096*4-1
    int tg = idx & 3;
    int gcol = (idx >> 2) & 4095;
    int kg = idx >> 14;
    int k0 = 16 * kg + 2 * tg;
    float v00 = Wh[(size_t)(k0) * G + gcol];
    float v01 = Wh[(size_t)(k0 + 1) * G + gcol];
    float v10 = Wh[(size_t)(k0 + 8) * G + gcol];
    float v11 = Wh[(size_t)(k0 + 9) * G + gcol];
    unsigned short h00, l00, h01, l01, h10, l10, h11, l11;
    split_bf(v00, h00, l00);
    split_bf(v01, h01, l01);
    split_bf(v10, h10, l10);
    split_bf(v11, h11, l11);
    g_Wsplit[idx] = make_uint4(pack2(h00, h01), pack2(h10, h11),
                               pack2(l00, l01), pack2(l10, l11));
}

// ---------------- input GEMM, 3xBF16, pre-split operands + reg-prefetch ----------------
// M=32768 (rows r=t*B+b), N=4096, K=1024. Tile 128x128, K-chunk 32 (16 kpairs).
// 256 threads = 8 warps (4M x 2N), warp tile 32x64.
__global__ __launch_bounds__(256) void gemm_in(const float* __restrict__ bias) {
    __shared__ unsigned As[2][128][20];   // [plane][row][kpair 0..15], stride 20 (16B-aligned rows)
    __shared__ unsigned Bs[2][128][20];   // [plane][ncol][kpair 0..15]

    const int bm = blockIdx.y, bn = blockIdx.x;
    const int tid = threadIdx.x;
    const int wid = tid >> 5, lane = tid & 31;
    const int wm = wid & 3, wn = wid >> 2;
    const int gq = lane >> 2, tg = lane & 3;

    // loader: per plane 512 uint4/chunk; thread handles idx = tid, tid+256
    const int l_row = tid >> 2;            // 0..63 (+64 second)
    const int l_kp4 = (tid & 3) << 2;      // kpair offset 0,4,8,12

    const unsigned* Ap[2] = {g_Apack[0] + (size_t)(bm * 128) * 512,
                             g_Apack[1] + (size_t)(bm * 128) * 512};
    const unsigned* Wp[2] = {g_Wpack[0] + (size_t)(bn * 128) * 512,
                             g_Wpack[1] + (size_t)(bn * 128) * 512};

    float acc[2][8][4];
#pragma unroll
    for (int mt = 0; mt < 2; mt++)
#pragma unroll
        for (int nt = 0; nt < 8; nt++)
#pragma unroll
            for (int q = 0; q < 4; q++) acc[mt][nt][q] = 0.0f;

    uint4 pa[2][2], pb[2][2];
#pragma unroll
    for (int pl = 0; pl < 2; pl++)
#pragma unroll
        for (int i = 0; i < 2; i++) {
            pa[pl][i] = *(const uint4*)(Ap[pl] + (size_t)(l_row + i * 64) * 512 + l_kp4);
            pb[pl][i] = *(const uint4*)(Wp[pl] + (size_t)(l_row + i * 64) * 512 + l_kp4);
        }

    for (int c = 0; c < 32; c++) {
#pragma unroll
        for (int pl = 0; pl < 2; pl++)
#pragma unroll
            for (int i = 0; i < 2; i++) {
                *(uint4*)&As[pl][l_row + i * 64][l_kp4] = pa[pl][i];
                *(uint4*)&Bs[pl][l_row + i * 64][l_kp4] = pb[pl][i];
            }
        __syncthreads();
        if (c < 31) {
            int kb = (c + 1) * 16 + l_kp4;
#pragma unroll
            for (int pl = 0; pl < 2; pl++)
#pragma unroll
                for (int i = 0; i < 2; i++) {
                    pa[pl][i] = *(const uint4*)(Ap[pl] + (size_t)(l_row + i * 64) * 512 + kb);
                    pb[pl][i] = *(const uint4*)(Wp[pl] + (size_t)(l_row + i * 64) * 512 + kb);
                }
        }
#pragma unroll
        for (int ks = 0; ks < 2; ks++) {
            unsigned ah[2][4], al[2][4];
#pragma unroll
            for (int mt = 0; mt < 2; mt++) {
                int row = wm * 32 + mt * 16;
                int cc = ks * 8;
                ah[mt][0] = As[0][row + gq][cc + tg];
                ah[mt][1] = As[0][row + gq + 8][cc + tg];
                ah[mt][2] = As[0][row + gq][cc + tg + 4];
                ah[mt][3] = As[0][row + gq + 8][cc + tg + 4];
                al[mt][0] = As[1][row + gq][cc + tg];
                al[mt][1] = As[1][row + gq + 8][cc + tg];
                al[mt][2] = As[1][row + gq][cc + tg + 4];
                al[mt][3] = As[1][row + gq + 8][cc + tg + 4];
            }
#pragma unroll
            for (int nt = 0; nt < 8; nt++) {
                int col = wn * 64 + nt * 8 + gq;
                unsigned bh[2], bl[2];
                bh[0] = Bs[0][col][ks * 8 + tg];
                bh[1] = Bs[0][col][ks * 8 + tg + 4];
                bl[0] = Bs[1][col][ks * 8 + tg];
                bl[1] = Bs[1][col][ks * 8 + tg + 4];
#pragma unroll
                for (int mt = 0; mt < 2; mt++) {
                    mma_bf16(acc[mt][nt], ah[mt], bh);
                    mma_bf16(acc[mt][nt], ah[mt], bl);
                    mma_bf16(acc[mt][nt], al[mt], bh);
                }
            }
        }
        __syncthreads();
    }

#pragma unroll
    for (int mt = 0; mt < 2; mt++) {
#pragma unroll
        for (int nt = 0; nt < 8; nt++) {
            int row = bm * 128 + wm * 32 + mt * 16 + gq;
            int col = bn * 128 + wn * 64 + nt * 8 + tg * 2;
            float b0v = bias[col], b1v = bias[col + 1];
            g_Zpre[(size_t)row * G + col]     = acc[mt][nt][0] + b0v;
            g_Zpre[(size_t)row * G + col + 1] = acc[mt][nt][1] + b1v;
            g_Zpre[(size_t)(row + 8) * G + col]     = acc[mt][nt][2] + b0v;
            g_Zpre[(size_t)(row + 8) * G + col + 1] = acc[mt][nt][3] + b1v;
        }
    }
}

// ---------------- persistent recurrence, 3xBF16, K-split x2 ----------------
// 128 blocks x 512 threads. Block owns 8 hidden units (32 gate cols).
// Warps 0-7: kg 0..31; warps 8-15: kg 32..63. Partials combined via smem.
__global__ __launch_bounds__(512) void lstm_persist(const int* __restrict__ lens,
                                                    int ymode,
                                                    float* __restrict__ yout) {
    __shared__ float Zs[2][64][36];
    __shared__ int   Ls[64];

    const int tid = threadIdx.x;
    const int wid = tid >> 5;
    const int lane = tid & 31;
    const int half = wid >> 3;
    const int wl = wid & 7;
    const int wm = wl & 3, wn = wl >> 2;
    const int gq = lane >> 2, tg = lane & 3;
    const int n0 = blockIdx.x * 8;
    const int kgbase = half * 32;

    if (tid < 64) Ls[tid] = read_len(lens, tid);
    __syncthreads();

    const int row0 = wm * 16;
    const int aoff0 = (row0 + gq) * 4 + tg;        // + kg*256
    const int aoff1 = (row0 + gq + 8) * 4 + tg;
    int gcol[2];
#pragma unroll
    for (int nt = 0; nt < 2; nt++) {
        int c = wn * 16 + nt * 8 + gq;             // local col 0..31
        gcol[nt] = ((c >> 3) * H + n0 + (c & 7)) * 4 + tg;  // + kg*16384
    }

    for (int t = 0; t < T; t++) {
        const float* __restrict__ h_in  = g_h[t & 1];
        float* __restrict__ h_out = g_h[(t + 1) & 1];
        const uint4* __restrict__ Ah = g_hsplit[t & 1];
        uint4* __restrict__ Aout = g_hsplit[(t + 1) & 1];
        const float* __restrict__ Zpre_t = g_Zpre + (size_t)t * B * G;

        float accA[2][4], accB[2][4];
#pragma unroll
        for (int nt = 0; nt < 2; nt++)
#pragma unroll
            for (int q = 0; q < 4; q++) { accA[nt][q] = 0.0f; accB[nt][q] = 0.0f; }

        uint4 a0 = __ldcg(Ah + kgbase * 256 + aoff0);
        uint4 a1 = __ldcg(Ah + kgbase * 256 + aoff1);
#pragma unroll 4
        for (int kg2 = 0; kg2 < 32; kg2++) {
            const int kg = kgbase + kg2;
            uint4 na0, na1;
            if (kg2 < 31) {
                na0 = __ldcg(Ah + (kg + 1) * 256 + aoff0);
                na1 = __ldcg(Ah + (kg + 1) * 256 + aoff1);
            }
            unsigned ah[4] = {a0.x, a1.x, a0.y, a1.y};
            unsigned al[4] = {a0.z, a1.z, a0.w, a1.w};
#pragma unroll
            for (int nt = 0; nt < 2; nt++) {
                uint4 bv = __ldg(g_Wsplit + kg * 16384 + gcol[nt]);
                unsigned bh[2] = {bv.x, bv.y};
                unsigned bl[2] = {bv.z, bv.w};
                mma_bf16(accA[nt], ah, bh);
                mma_bf16(accB[nt], ah, bl);
                mma_bf16(accA[nt], al, bh);
            }
            a0 = na0; a1 = na1;
        }

        // partial z tile per half
#pragma unroll
        for (int nt = 0; nt < 2; nt++) {
            int row = wm * 16 + gq;
            int col = wn * 16 + nt * 8 + tg * 2;
            Zs[half][row][col]     = accA[nt][0] + accB[nt][0];
            Zs[half][row][col + 1] = accA[nt][1] + accB[nt][1];
            Zs[half][row + 8][col]     = accA[nt][2] + accB[nt][2];
            Zs[half][row + 8][col + 1] = accA[nt][3] + accB[nt][3];
        }
        __syncthreads();

        // fused gates + masking; 64 batch x 8 units = 512 items, 1 per thread
        {
            int b = tid >> 3;
            int nn = tid & 7;
            int n = n0 + nn;
            size_t zb = (size_t)b * G;
            float zi = Zs[0][b][0 * 8 + nn] + Zs[1][b][0 * 8 + nn] + Zpre_t[zb + 0 * H + n];
            float zj = Zs[0][b][1 * 8 + nn] + Zs[1][b][1 * 8 + nn] + Zpre_t[zb + 1 * H + n];
            float zf = Zs[0][b][2 * 8 + nn] + Zs[1][b][2 * 8 + nn] + Zpre_t[zb + 2 * H + n];
            float zo = Zs[0][b][3 * 8 + nn] + Zs[1][b][3 * 8 + nn] + Zpre_t[zb + 3 * H + n];
            size_t hi = (size_t)b * H + n;
            bool m = t < Ls[b];
            float yv = 0.0f;
            float newh;
            if (m) {
                float cv = g_c[hi];
                float cn = cv * sigf(zf + 1.0f) + sigf(zi) * tanhf(zj);
                newh = tanhf(cn) * sigf(zo);
                g_c[hi] = cn;
                yv = newh;
            } else {
                newh = __ldcg(h_in + hi);
            }
            h_out[hi] = newh;
            // packed bf16 split write of newh for next step's A-fragments
            {
                int kg = n >> 4;
                int k15 = n & 15;
                int tg2 = (k15 & 7) >> 1;
                int cbit = k15 & 1;
                int w = k15 >> 3;
                unsigned short hu, lu;
                split_bf(newh, hu, lu);
                unsigned short* base = (unsigned short*)(Aout + (kg * 64 + b) * 4 + tg2);
                base[w * 2 + cbit]     = hu;
                base[4 + w * 2 + cbit] = lu;
            }
            if (ymode == 0) {
                // write y0 in packed Apack form for layer-1 GEMM
                size_t r = (size_t)t * B + b;
                unsigned short hu, lu;
                split_bf(yv, hu, lu);
                ((unsigned short*)(g_Apack[0] + r * 512 + (n >> 1)))[n & 1] = hu;
                ((unsigned short*)(g_Apack[1] + r * 512 + (n >> 1)))[n & 1] = lu;
            } else {
                yout[((size_t)b * T + t) * H + n] = yv;
            }
        }

        grid_sync();
    }
}

// ---------------- final h/c copy ----------------
__global__ void copy_hc(float* __restrict__ out_h, float* __restrict__ out_c) {
    int i = blockIdx.x * 256 + threadIdx.x;
    if (i < B * H) { out_h[i] = g_h[0][i]; out_c[i] = g_c[i]; }
}

// ---------------- launch ----------------
extern "C" void kernel_launch(void* const* d_in, const int* in_sizes, int n_in,
                              void* d_out, int out_size) {
    const float* x = nullptr;
    const int* lengths = nullptr;
    const float* W0 = nullptr; const float* b0 = nullptr;
    const float* W1 = nullptr; const float* b1 = nullptr;
    int wseen = 0, bseen = 0;
    for (int i = 0; i < n_in; i++) {
        long long s = in_sizes[i];
        if (s == (long long)B * T * D) x = (const float*)d_in[i];
        else if (s == B) lengths = (const int*)d_in[i];
        else if (s == (long long)(D + H) * G) {
            if (wseen++ == 0) W0 = (const float*)d_in[i];
            else W1 = (const float*)d_in[i];
        } else if (s == G) {
            if (bseen++ == 0) b0 = (const float*)d_in[i];
            else b1 = (const float*)d_in[i];
        }
    }

    float* out = (float*)d_out;
    float* out_y = out;
    float* out_h = out + (size_t)B * T * H;      // h_stack [2][B][H]
    float* out_c = out_h + 2 * B * H;            // c_stack [2][B][H]

    const int sgrid = (B * H + 255) / 256;
    dim3 ggrid(G / 128, (B * T) / 128);          // 32 x 256
    const int wgrid = (64 * G * 4) / 256;
    const int xgrid = (B * T * 512) / 256;       // 65536
    const int wingrid = (G * 512) / 256;         // 8192

    // ---- layer 0 ----
    init_state<<<sgrid, 256>>>();
    split_x<<<xgrid, 256>>>(x);
    split_Win<<<wingrid, 256>>>(W0);
    split_W<<<wgrid, 256>>>(W0 + (size_t)D * G);
    gemm_in<<<ggrid, 256>>>(b0);
    lstm_persist<<<PBLOCKS, 512>>>(lengths, 0, nullptr);
    copy_hc<<<sgrid, 256>>>(out_h, out_c);

    // ---- layer 1 ----
    init_state<<<sgrid, 256>>>();
    split_Win<<<wingrid, 256>>>(W1);
    split_W<<<wgrid, 256>>>(W1 + (size_t)H * G);
    gemm_in<<<ggrid, 256>>>(b1);
    lstm_persist<<<PBLOCKS, 512>>>(lengths, 1, out_y);
    copy_hc<<<sgrid, 256>>>(out_h + B * H, out_c + B * H);
}

// round 14
// speedup vs baseline: 4.0301x; 1.2066x over previous
#include <cuda_runtime.h>
#include <cuda_bf16.h>
#include <cstdint>

#define B 64
#define T 512
#define D 1024
#define H 1024
#define G 4096      // 4*H
#define PBLOCKS 128 // persistent grid size (<=148 SMs -> co-resident)

// ---------------- device scratch (no allocations allowed) ----------------
__device__ float g_Zpre[(size_t)T * B * G];        // [t][b][4H] pre-activations
__device__ float g_h[2][B * H];                    // ping-pong hidden state (fp32)
__device__ float g_c[B * H];                       // cell state
// packed bf16x2 planes for the input GEMM:
__device__ unsigned g_Apack[2][(size_t)B * T * 512];   // 134 MB
__device__ unsigned g_Wpack[2][(size_t)G * 512];       // 16 MB
// packed operands for the recurrence (validated layout):
__device__ uint4 g_hsplit[2][64 * B * 4];
__device__ uint4 g_Wsplit[64 * G * 4];                 // 16 MB
__device__ volatile int g_bar_count = 0;
__device__ volatile int g_bar_gen = 0;

// ---------------- helpers ----------------
__device__ __forceinline__ void split_bf(float v, unsigned short& h, unsigned short& l) {
    __nv_bfloat16 hb = __float2bfloat16_rn(v);
    float r = v - __bfloat162float(hb);
    __nv_bfloat16 lb = __float2bfloat16_rn(r);
    h = *(unsigned short*)&hb;
    l = *(unsigned short*)&lb;
}

__device__ __forceinline__ unsigned pack2(unsigned short a, unsigned short b) {
    return (unsigned)a | ((unsigned)b << 16);
}

__device__ __forceinline__ void mma_bf16(float c[4], const unsigned a[4], const unsigned b[2]) {
    asm volatile(
        "mma.sync.aligned.m16n8k16.row.col.f32.bf16.bf16.f32 "
        "{%0,%1,%2,%3}, {%4,%5,%6,%7}, {%8,%9}, {%0,%1,%2,%3};"
        : "+f"(c[0]), "+f"(c[1]), "+f"(c[2]), "+f"(c[3])
        : "r"(a[0]), "r"(a[1]), "r"(a[2]), "r"(a[3]), "r"(b[0]), "r"(b[1]));
}

__device__ __forceinline__ float sigf(float x) {
    return 1.0f / (1.0f + __expf(-x));
}

__device__ __forceinline__ int read_len(const int* p, int b) {
    int is64 = (p[1] == 0);
    return is64 ? p[2 * b] : p[b];
}

__device__ __forceinline__ void grid_sync() {
    __threadfence();
    __syncthreads();
    if (threadIdx.x == 0) {
        int gen = g_bar_gen;
        if (atomicAdd((int*)&g_bar_count, 1) == PBLOCKS - 1) {
            g_bar_count = 0;
            __threadfence();
            g_bar_gen = gen + 1;
        } else {
            while (g_bar_gen == gen) { __nanosleep(32); }
        }
        __threadfence();
    }
    __syncthreads();
}

// ---------------- init ----------------
__global__ void init_state() {
    int i = blockIdx.x * 256 + threadIdx.x;
    if (i < B * H) { g_h[0][i] = 0.0f; g_c[i] = 0.0f; }
    if (i < 64 * B * 4) g_hsplit[0][i] = make_uint4(0, 0, 0, 0);
}

// ---------------- pre-split x into Apack ----------------
__global__ void split_x(const float* __restrict__ x) {
    size_t idx = (size_t)blockIdx.x * 256 + threadIdx.x;   // over B*T*512
    int kp = (int)(idx & 511);
    size_t r = idx >> 9;
    int b = (int)(r & 63);
    int t = (int)(r >> 6);
    float2 v = *(const float2*)(x + ((size_t)b * T + t) * D + 2 * kp);
    unsigned short h0, l0, h1, l1;
    split_bf(v.x, h0, l0);
    split_bf(v.y, h1, l1);
    g_Apack[0][idx] = pack2(h0, h1);
    g_Apack[1][idx] = pack2(l0, l1);
}

// ---------------- pre-split input-part of W into Wpack ----------------
__global__ void split_Win(const float* __restrict__ W) {
    size_t idx = (size_t)blockIdx.x * 256 + threadIdx.x;   // over G*512
    int col = (int)(idx & 4095);
    int kp = (int)(idx >> 12);
    float v0 = W[(size_t)(2 * kp) * G + col];
    float v1 = W[(size_t)(2 * kp + 1) * G + col];
    unsigned short h0, l0, h1, l1;
    split_bf(v0, h0, l0);
    split_bf(v1, h1, l1);
    g_Wpack[0][(size_t)col * 512 + kp] = pack2(h0, h1);
    g_Wpack[1][(size_t)col * 512 + kp] = pack2(l0, l1);
}

// ---------------- pre-split recurrent Wh (validated layout) ----------------
__global__ void split_W(const float* __restrict__ Wh) {
    int idx = blockIdx.x * 256 + threadIdx.x;   // 0 .. 64*4096*4-1
    int tg = idx & 3;
    int gcol = (idx >> 2) & 4095;
    int kg = idx >> 14;
    int k0 = 16 * kg + 2 * tg;
    float v00 = Wh[(size_t)(k0) * G + gcol];
    float v01 = Wh[(size_t)(k0 + 1) * G + gcol];
    float v10 = Wh[(size_t)(k0 + 8) * G + gcol];
    float v11 = Wh[(size_t)(k0 + 9) * G + gcol];
    unsigned short h00, l00, h01, l01, h10, l10, h11, l11;
    split_bf(v00, h00, l00);
    split_bf(v01, h01, l01);
    split_bf(v10, h10, l10);
    split_bf(v11, h11, l11);
    g_Wsplit[idx] = make_uint4(pack2(h00, h01), pack2(h10, h11),
                               pack2(l00, l01), pack2(l10, l11));
}

// ---------------- input GEMM, 3xBF16 (validated round 11) ----------------
__global__ __launch_bounds__(256) void gemm_in(const float* __restrict__ bias) {
    __shared__ unsigned As[2][128][20];
    __shared__ unsigned Bs[2][128][20];

    const int bm = blockIdx.y, bn = blockIdx.x;
    const int tid = threadIdx.x;
    const int wid = tid >> 5, lane = tid & 31;
    const int wm = wid & 3, wn = wid >> 2;
    const int gq = lane >> 2, tg = lane & 3;

    const int l_row = tid >> 2;
    const int l_kp4 = (tid & 3) << 2;

    const unsigned* Ap[2] = {g_Apack[0] + (size_t)(bm * 128) * 512,
                             g_Apack[1] + (size_t)(bm * 128) * 512};
    const unsigned* Wp[2] = {g_Wpack[0] + (size_t)(bn * 128) * 512,
                             g_Wpack[1] + (size_t)(bn * 128) * 512};

    float acc[2][8][4];
#pragma unroll
    for (int mt = 0; mt < 2; mt++)
#pragma unroll
        for (int nt = 0; nt < 8; nt++)
#pragma unroll
            for (int q = 0; q < 4; q++) acc[mt][nt][q] = 0.0f;

    uint4 pa[2][2], pb[2][2];
#pragma unroll
    for (int pl = 0; pl < 2; pl++)
#pragma unroll
        for (int i = 0; i < 2; i++) {
            pa[pl][i] = *(const uint4*)(Ap[pl] + (size_t)(l_row + i * 64) * 512 + l_kp4);
            pb[pl][i] = *(const uint4*)(Wp[pl] + (size_t)(l_row + i * 64) * 512 + l_kp4);
        }

    for (int c = 0; c < 32; c++) {
#pragma unroll
        for (int pl = 0; pl < 2; pl++)
#pragma unroll
            for (int i = 0; i < 2; i++) {
                *(uint4*)&As[pl][l_row + i * 64][l_kp4] = pa[pl][i];
                *(uint4*)&Bs[pl][l_row + i * 64][l_kp4] = pb[pl][i];
            }
        __syncthreads();
        if (c < 31) {
            int kb = (c + 1) * 16 + l_kp4;
#pragma unroll
            for (int pl = 0; pl < 2; pl++)
#pragma unroll
                for (int i = 0; i < 2; i++) {
                    pa[pl][i] = *(const uint4*)(Ap[pl] + (size_t)(l_row + i * 64) * 512 + kb);
                    pb[pl][i] = *(const uint4*)(Wp[pl] + (size_t)(l_row + i * 64) * 512 + kb);
                }
        }
#pragma unroll
        for (int ks = 0; ks < 2; ks++) {
            unsigned ah[2][4], al[2][4];
#pragma unroll
            for (int mt = 0; mt < 2; mt++) {
                int row = wm * 32 + mt * 16;
                int cc = ks * 8;
                ah[mt][0] = As[0][row + gq][cc + tg];
                ah[mt][1] = As[0][row + gq + 8][cc + tg];
                ah[mt][2] = As[0][row + gq][cc + tg + 4];
                ah[mt][3] = As[0][row + gq + 8][cc + tg + 4];
                al[mt][0] = As[1][row + gq][cc + tg];
                al[mt][1] = As[1][row + gq + 8][cc + tg];
                al[mt][2] = As[1][row + gq][cc + tg + 4];
                al[mt][3] = As[1][row + gq + 8][cc + tg + 4];
            }
#pragma unroll
            for (int nt = 0; nt < 8; nt++) {
                int col = wn * 64 + nt * 8 + gq;
                unsigned bh[2], bl[2];
                bh[0] = Bs[0][col][ks * 8 + tg];
                bh[1] = Bs[0][col][ks * 8 + tg + 4];
                bl[0] = Bs[1][col][ks * 8 + tg];
                bl[1] = Bs[1][col][ks * 8 + tg + 4];
#pragma unroll
                for (int mt = 0; mt < 2; mt++) {
                    mma_bf16(acc[mt][nt], ah[mt], bh);
                    mma_bf16(acc[mt][nt], ah[mt], bl);
                    mma_bf16(acc[mt][nt], al[mt], bh);
                }
            }
        }
        __syncthreads();
    }

#pragma unroll
    for (int mt = 0; mt < 2; mt++) {
#pragma unroll
        for (int nt = 0; nt < 8; nt++) {
            int row = bm * 128 + wm * 32 + mt * 16 + gq;
            int col = bn * 128 + wn * 64 + nt * 8 + tg * 2;
            float b0v = bias[col], b1v = bias[col + 1];
            g_Zpre[(size_t)row * G + col]     = acc[mt][nt][0] + b0v;
            g_Zpre[(size_t)row * G + col + 1] = acc[mt][nt][1] + b1v;
            g_Zpre[(size_t)(row + 8) * G + col]     = acc[mt][nt][2] + b0v;
            g_Zpre[(size_t)(row + 8) * G + col + 1] = acc[mt][nt][3] + b1v;
        }
    }
}

// ---------------- persistent recurrence, 3xBF16, zero-duplication tiling ----------------
// 128 blocks x 256 threads (8 warps). Block owns 8 hidden units (32 gate cols).
// Warp w = K-slice kg in [8w, 8w+8); warp tile M=64 (4 m-tiles) x N=32 (4 n-tiles).
// No fragment is loaded twice anywhere in the block. Partials in dynamic smem.
#define ZS_STRIDE 36
__global__ __launch_bounds__(256) void lstm_persist(const int* __restrict__ lens,
                                                    int ymode,
                                                    float* __restrict__ yout) {
    extern __shared__ float Zsd[];    // [8][64][ZS_STRIDE] partial z tiles
    __shared__ int Ls[64];

    const int tid = threadIdx.x;
    const int wid = tid >> 5;
    const int lane = tid & 31;
    const int gq = lane >> 2, tg = lane & 3;
    const int n0 = blockIdx.x * 8;
    const int kgbase = wid * 8;

    if (tid < 64) Ls[tid] = read_len(lens, tid);
    __syncthreads();

    // per-lane fragment offsets
    int aoff[4][2];
#pragma unroll
    for (int mt = 0; mt < 4; mt++) {
        aoff[mt][0] = (16 * mt + gq) * 4 + tg;        // + kg*256
        aoff[mt][1] = (16 * mt + gq + 8) * 4 + tg;
    }
    int gcol[4];
#pragma unroll
    for (int nt = 0; nt < 4; nt++)
        gcol[nt] = (nt * H + n0 + gq) * 4 + tg;       // + kg*16384

    for (int t = 0; t < T; t++) {
        const float* __restrict__ h_in  = g_h[t & 1];
        float* __restrict__ h_out = g_h[(t + 1) & 1];
        const uint4* __restrict__ Ah = g_hsplit[t & 1];
        uint4* __restrict__ Aout = g_hsplit[(t + 1) & 1];
        const float* __restrict__ Zpre_t = g_Zpre + (size_t)t * B * G;

        float acc[4][4][4];
#pragma unroll
        for (int mt = 0; mt < 4; mt++)
#pragma unroll
            for (int nt = 0; nt < 4; nt++)
#pragma unroll
                for (int q = 0; q < 4; q++) acc[mt][nt][q] = 0.0f;

        uint4 av[4][2], wv[4];
        {
            const uint4* Ak = Ah + kgbase * 256;
#pragma unroll
            for (int mt = 0; mt < 4; mt++) {
                av[mt][0] = __ldcg(Ak + aoff[mt][0]);
                av[mt][1] = __ldcg(Ak + aoff[mt][1]);
            }
            const uint4* Wk = g_Wsplit + kgbase * 16384;
#pragma unroll
            for (int nt = 0; nt < 4; nt++) wv[nt] = __ldg(Wk + gcol[nt]);
        }

#pragma unroll
        for (int kg2 = 0; kg2 < 8; kg2++) {
            uint4 nav[4][2], nwv[4];
            if (kg2 < 7) {
                const int kg = kgbase + kg2 + 1;
                const uint4* Ak = Ah + kg * 256;
#pragma unroll
                for (int mt = 0; mt < 4; mt++) {
                    nav[mt][0] = __ldcg(Ak + aoff[mt][0]);
                    nav[mt][1] = __ldcg(Ak + aoff[mt][1]);
                }
                const uint4* Wk = g_Wsplit + kg * 16384;
#pragma unroll
                for (int nt = 0; nt < 4; nt++) nwv[nt] = __ldg(Wk + gcol[nt]);
            }
#pragma unroll
            for (int nt = 0; nt < 4; nt++) {
                unsigned bh[2] = {wv[nt].x, wv[nt].y};
                unsigned bl[2] = {wv[nt].z, wv[nt].w};
#pragma unroll
                for (int mt = 0; mt < 4; mt++) {
                    unsigned ah[4] = {av[mt][0].x, av[mt][1].x, av[mt][0].y, av[mt][1].y};
                    unsigned al[4] = {av[mt][0].z, av[mt][1].z, av[mt][0].w, av[mt][1].w};
                    mma_bf16(acc[mt][nt], ah, bh);
                    mma_bf16(acc[mt][nt], ah, bl);
                    mma_bf16(acc[mt][nt], al, bh);
                }
            }
#pragma unroll
            for (int mt = 0; mt < 4; mt++) { av[mt][0] = nav[mt][0]; av[mt][1] = nav[mt][1]; }
#pragma unroll
            for (int nt = 0; nt < 4; nt++) wv[nt] = nwv[nt];
        }

        // store partial z tile for this warp's K-slice
        float* Zw = Zsd + (size_t)wid * 64 * ZS_STRIDE;
#pragma unroll
        for (int mt = 0; mt < 4; mt++) {
#pragma unroll
            for (int nt = 0; nt < 4; nt++) {
                int row = 16 * mt + gq;
                int col = nt * 8 + tg * 2;
                Zw[row * ZS_STRIDE + col]     = acc[mt][nt][0];
                Zw[row * ZS_STRIDE + col + 1] = acc[mt][nt][1];
                Zw[(row + 8) * ZS_STRIDE + col]     = acc[mt][nt][2];
                Zw[(row + 8) * ZS_STRIDE + col + 1] = acc[mt][nt][3];
            }
        }
        __syncthreads();

        // fused gates + masking; 64 batch x 8 units = 512 items, 2 per thread
#pragma unroll
        for (int p = 0; p < 2; p++) {
            int it = tid + p * 256;
            int b = it >> 3;
            int nn = it & 7;
            int n = n0 + nn;
            size_t zb = (size_t)b * G;
            float zi = Zpre_t[zb + 0 * H + n];
            float zj = Zpre_t[zb + 1 * H + n];
            float zf = Zpre_t[zb + 2 * H + n];
            float zo = Zpre_t[zb + 3 * H + n];
#pragma unroll
            for (int w = 0; w < 8; w++) {
                const float* Zw = Zsd + ((size_t)w * 64 + b) * ZS_STRIDE;
                zi += Zw[0 * 8 + nn];
                zj += Zw[1 * 8 + nn];
                zf += Zw[2 * 8 + nn];
                zo += Zw[3 * 8 + nn];
            }
            size_t hi = (size_t)b * H + n;
            bool m = t < Ls[b];
            float yv = 0.0f;
            float newh;
            if (m) {
                float cv = g_c[hi];
                float cn = cv * sigf(zf + 1.0f) + sigf(zi) * tanhf(zj);
                newh = tanhf(cn) * sigf(zo);
                g_c[hi] = cn;
                yv = newh;
            } else {
                newh = __ldcg(h_in + hi);
            }
            h_out[hi] = newh;
            // packed bf16 split write of newh for next step's A-fragments
            {
                int kg = n >> 4;
                int k15 = n & 15;
                int tg2 = (k15 & 7) >> 1;
                int cbit = k15 & 1;
                int w = k15 >> 3;
                unsigned short hu, lu;
                split_bf(newh, hu, lu);
                unsigned short* base = (unsigned short*)(Aout + (kg * 64 + b) * 4 + tg2);
                base[w * 2 + cbit]     = hu;
                base[4 + w * 2 + cbit] = lu;
            }
            if (ymode == 0) {
                size_t r = (size_t)t * B + b;
                unsigned short hu, lu;
                split_bf(yv, hu, lu);
                ((unsigned short*)(g_Apack[0] + r * 512 + (n >> 1)))[n & 1] = hu;
                ((unsigned short*)(g_Apack[1] + r * 512 + (n >> 1)))[n & 1] = lu;
            } else {
                yout[((size_t)b * T + t) * H + n] = yv;
            }
        }

        grid_sync();
    }
}

// ---------------- final h/c copy ----------------
__global__ void copy_hc(float* __restrict__ out_h, float* __restrict__ out_c) {
    int i = blockIdx.x * 256 + threadIdx.x;
    if (i < B * H) { out_h[i] = g_h[0][i]; out_c[i] = g_c[i]; }
}

// ---------------- launch ----------------
extern "C" void kernel_launch(void* const* d_in, const int* in_sizes, int n_in,
                              void* d_out, int out_size) {
    const float* x = nullptr;
    const int* lengths = nullptr;
    const float* W0 = nullptr; const float* b0 = nullptr;
    const float* W1 = nullptr; const float* b1 = nullptr;
    int wseen = 0, bseen = 0;
    for (int i = 0; i < n_in; i++) {
        long long s = in_sizes[i];
        if (s == (long long)B * T * D) x = (const float*)d_in[i];
        else if (s == B) lengths = (const int*)d_in[i];
        else if (s == (long long)(D + H) * G) {
            if (wseen++ == 0) W0 = (const float*)d_in[i];
            else W1 = (const float*)d_in[i];
        } else if (s == G) {
            if (bseen++ == 0) b0 = (const float*)d_in[i];
            else b1 = (const float*)d_in[i];
        }
    }

    float* out = (float*)d_out;
    float* out_y = out;
    float* out_h = out + (size_t)B * T * H;      // h_stack [2][B][H]
    float* out_c = out_h + 2 * B * H;            // c_stack [2][B][H]

    const size_t zs_bytes = 8 * 64 * ZS_STRIDE * sizeof(float);   // 73728
    cudaFuncSetAttribute(lstm_persist, cudaFuncAttributeMaxDynamicSharedMemorySize,
                         (int)zs_bytes);

    const int sgrid = (B * H + 255) / 256;
    dim3 ggrid(G / 128, (B * T) / 128);          // 32 x 256
    const int wgrid = (64 * G * 4) / 256;
    const int xgrid = (B * T * 512) / 256;       // 65536
    const int wingrid = (G * 512) / 256;         // 8192

    // ---- layer 0 ----
    init_state<<<sgrid, 256>>>();
    split_x<<<xgrid, 256>>>(x);
    split_Win<<<wingrid, 256>>>(W0);
    split_W<<<wgrid, 256>>>(W0 + (size_t)D * G);
    gemm_in<<<ggrid, 256>>>(b0);
    lstm_persist<<<PBLOCKS, 256, zs_bytes>>>(lengths, 0, nullptr);
    copy_hc<<<sgrid, 256>>>(out_h, out_c);

    // ---- layer 1 ----
    init_state<<<sgrid, 256>>>();
    split_Win<<<wingrid, 256>>>(W1);
    split_W<<<wgrid, 256>>>(W1 + (size_t)H * G);
    gemm_in<<<ggrid, 256>>>(b1);
    lstm_persist<<<PBLOCKS, 256, zs_bytes>>>(lengths, 1, out_y);
    copy_hc<<<sgrid, 256>>>(out_h + B * H, out_c + B * H);
}